// round 11
// baseline (speedup 1.0000x reference)
#include <cuda_runtime.h>
#include <cuda_fp16.h>
#include <math.h>
#include <stdint.h>

// Problem dims (fixed): B=2, N=2048, C=1024, H=16, D=64, FF=4096
#define MTOT 4096
#define CDIM 1024
#define FFDIM 4096
#define NSEQ 2048
#define NHEAD 16
#define HDIM 64
#define QKVN 3072

// ---------------- scratch (no allocations -> __device__ globals) ------------
__device__ __half g_xn  [MTOT*CDIM];
__device__ __half g_qkvh[MTOT*QKVN];
__device__ __half g_qb  [MTOT*CDIM], g_kb[MTOT*CDIM], g_vb[MTOT*CDIM];
__device__ __half g_ctx [MTOT*CDIM];
__device__ float  g_x2  [MTOT*CDIM];
__device__ __half g_xn2 [MTOT*CDIM];
__device__ __half g_h   [MTOT*FFDIM];
__device__ __half g_wqkv[QKVN*CDIM];
__device__ __half g_wo  [CDIM*CDIM];
__device__ __half g_w1  [FFDIM*CDIM];
__device__ __half g_w2  [CDIM*FFDIM];
__device__ float  g_bqkv[QKVN];

// ---------------- helpers ----------------------------------------------------
__device__ __forceinline__ uint32_t smem_u32(const void* p) {
    uint32_t a;
    asm("{ .reg .u64 t; cvta.to.shared.u64 t, %1; cvt.u32.u64 %0, t; }"
        : "=r"(a) : "l"(p));
    return a;
}
__device__ __forceinline__ void ldmat4(uint32_t (&r)[4], uint32_t addr) {
    asm volatile("ldmatrix.sync.aligned.m8n8.x4.shared.b16 {%0,%1,%2,%3}, [%4];"
                 : "=r"(r[0]), "=r"(r[1]), "=r"(r[2]), "=r"(r[3]) : "r"(addr));
}
__device__ __forceinline__ void ldmat4t(uint32_t (&r)[4], uint32_t addr) {
    asm volatile("ldmatrix.sync.aligned.m8n8.x4.trans.shared.b16 {%0,%1,%2,%3}, [%4];"
                 : "=r"(r[0]), "=r"(r[1]), "=r"(r[2]), "=r"(r[3]) : "r"(addr));
}
__device__ __forceinline__ void mma16816(float (&d)[4], const uint32_t (&a)[4],
                                         uint32_t b0, uint32_t b1) {
    asm volatile(
        "mma.sync.aligned.m16n8k16.row.col.f32.f16.f16.f32 "
        "{%0,%1,%2,%3}, {%4,%5,%6,%7}, {%8,%9}, {%0,%1,%2,%3};"
        : "+f"(d[0]), "+f"(d[1]), "+f"(d[2]), "+f"(d[3])
        : "r"(a[0]), "r"(a[1]), "r"(a[2]), "r"(a[3]), "r"(b0), "r"(b1));
}
__device__ __forceinline__ uint32_t pckh(__half a, __half b) {
    __half2 t(a, b);
    return *reinterpret_cast<uint32_t*>(&t);
}
__device__ __forceinline__ uint32_t pckf(float a, float b) {
    return pckh(__float2half(a), __float2half(b));
}
__device__ __forceinline__ float ex2f(float x) {
    float y;
    asm("ex2.approx.f32 %0, %1;" : "=f"(y) : "f"(x));
    return y;
}
__device__ __forceinline__ float gelu_exact(float x) {
    return 0.5f * x * (1.0f + erff(x * 0.7071067811865476f));
}
__device__ __forceinline__ void cp16(uint32_t d, const void* s) {
    asm volatile("cp.async.cg.shared.global [%0], [%1], 16;" :: "r"(d), "l"(s));
}
__device__ __forceinline__ void cpcommit() {
    asm volatile("cp.async.commit_group;" ::: "memory");
}
__device__ __forceinline__ void cpwait0() {
    asm volatile("cp.async.wait_group 0;" ::: "memory");
}
__device__ __forceinline__ void cpwait1() {
    asm volatile("cp.async.wait_group 1;" ::: "memory");
}
__device__ __forceinline__ void cpwait2() {
    asm volatile("cp.async.wait_group 2;" ::: "memory");
}

// ---------------- misc small kernels -----------------------------------------
__global__ void bias_concat_kernel(const float* bq, const float* bk,
                                   const float* bv, float* out)
{
    const int i = blockIdx.x * 256 + threadIdx.x;
    float v;
    if (i < 1024)      v = bq[i];
    else if (i < 2048) v = bk[i - 1024];
    else               v = bv[i - 2048];
    out[i] = v;
}

// fast transpose: 64x64 tiles, float4 loads, coalesced half2 stores
// out[c][r] = fp16(in[r][c]); R = input rows, Cc = input cols
__global__ __launch_bounds__(256) void transpose_h2_kernel(
    const float* __restrict__ in, __half* __restrict__ o, int R, int Cc)
{
    __shared__ float ts[64][65];
    const int tx = threadIdx.x, ty = threadIdx.y;     // (32, 8)
    const int t  = ty * 32 + tx;
    const int c0 = blockIdx.x * 64, r0 = blockIdx.y * 64;

    #pragma unroll
    for (int i = 0; i < 4; i++) {
        const int idx = i * 256 + t;          // 0..1023
        const int row = idx >> 4;             // 0..63
        const int c4  = idx & 15;             // float4 col
        float4 f = *reinterpret_cast<const float4*>(
            in + (size_t)(r0 + row) * Cc + c0 + c4 * 4);
        ts[row][c4*4+0] = f.x; ts[row][c4*4+1] = f.y;
        ts[row][c4*4+2] = f.z; ts[row][c4*4+3] = f.w;
    }
    __syncthreads();

    #pragma unroll
    for (int i = 0; i < 8; i++) {
        const int cc = ty + 8 * i;            // 0..63 (output row)
        const int rr = tx * 2;                // output col pair
        const uint32_t h2 = pckf(ts[rr][cc], ts[rr + 1][cc]);
        *reinterpret_cast<uint32_t*>(o + (size_t)(c0 + cc) * R + r0 + rr) = h2;
    }
}

__global__ __launch_bounds__(256) void rmsnorm_h_kernel(
    const float* __restrict__ x, const float* __restrict__ scale,
    __half* __restrict__ o)
{
    __shared__ float red[8];
    const int row = blockIdx.x;
    const int t   = threadIdx.x;
    const float* xr = x + (size_t)row * CDIM;

    float4 v = *reinterpret_cast<const float4*>(xr + t * 4);
    float ss = v.x * v.x + v.y * v.y + v.z * v.z + v.w * v.w;
    #pragma unroll
    for (int of = 16; of > 0; of >>= 1) ss += __shfl_xor_sync(0xffffffffu, ss, of);
    if ((t & 31) == 0) red[t >> 5] = ss;
    __syncthreads();
    if (t < 8) {
        float s2 = red[t];
        #pragma unroll
        for (int of = 4; of > 0; of >>= 1) s2 += __shfl_xor_sync(0xffu, s2, of);
        if (t == 0) red[0] = s2;
    }
    __syncthreads();
    const float norm = sqrtf(red[0]);
    const float inv  = 1.0f / (norm * 0.03125f + 1e-8f);

    float4 sc = *reinterpret_cast<const float4*>(scale + t * 4);
    uint2 w;
    w.x = pckf(v.x * sc.x * inv, v.y * sc.y * inv);
    w.y = pckf(v.z * sc.z * inv, v.w * sc.w * inv);
    *reinterpret_cast<uint2*>(o + (size_t)row * CDIM + t * 4) = w;
}

// post-QKV v2: 4 threads per head-row, roll neighbor via shfl
__global__ __launch_bounds__(256) void postqkv_kernel(
    const __half* __restrict__ qkv, __half* __restrict__ qb,
    __half* __restrict__ kb, __half* __restrict__ vb)
{
    const int id   = blockIdx.x * 256 + threadIdx.x;
    const int sec  = blockIdx.y;
    const int row  = id >> 2;
    const int part = id & 3;
    const int lane = threadIdx.x & 31;
    const int m    = row >> 4;
    const int h    = row & 15;
    const __half* src = qkv + (size_t)m * QKVN + sec * 1024 + h * HDIM + part * 16;
    __half* dst = (sec == 0 ? qb : sec == 1 ? kb : vb)
                  + (size_t)m * CDIM + h * HDIM + part * 16;

    float f[16];
    #pragma unroll
    for (int i = 0; i < 2; i++) {
        uint4 w = *reinterpret_cast<const uint4*>(src + i * 8);
        const __half2* hp = reinterpret_cast<const __half2*>(&w);
        #pragma unroll
        for (int p = 0; p < 4; p++) {
            float2 ff = __half22float2(hp[p]);
            f[i*8 + p*2 + 0] = ff.x;
            f[i*8 + p*2 + 1] = ff.y;
        }
    }

    float o[16];
    if (sec == 2) {
        #pragma unroll
        for (int d = 0; d < 16; d++) o[d] = f[d];
    } else {
        const int srcl = (lane & ~3) | ((part + 3) & 3);
        const float prevv = __shfl_sync(0xffffffffu, f[15], srcl);
        o[0] = f[0] - prevv;
        #pragma unroll
        for (int d = 1; d < 16; d++) o[d] = f[d] - f[d - 1];
        if (sec == 0) {
            const float cscale = 0.125f * 1.4426950408889634f;
            #pragma unroll
            for (int d = 0; d < 16; d++) o[d] *= cscale;
        }
    }
    #pragma unroll
    for (int i = 0; i < 2; i++) {
        uint4 w;
        w.x = pckf(o[i*8+0], o[i*8+1]);
        w.y = pckf(o[i*8+2], o[i*8+3]);
        w.z = pckf(o[i*8+4], o[i*8+5]);
        w.w = pckf(o[i*8+6], o[i*8+7]);
        *reinterpret_cast<uint4*>(dst + i * 8) = w;
    }
}

// ---------------- GEMM v4b: fp16, 3-stage cp.async, early prefetch ----------
#define PITCH 40
#define TILEB (128 * PITCH * 2)     // 10240 B
#define STAGEB (2 * TILEB)          // 20480 B (A + B)
#define GSMEM (3 * STAGEB)          // 61440 B

template <int EPI>
__global__ __launch_bounds__(256, 2) void gemm4_kernel(
    const __half* __restrict__ A, const __half* __restrict__ Bw,
    const float* __restrict__ bias, const float* __restrict__ res,
    float* __restrict__ Co, __half* __restrict__ Ch, int M, int Nn, int K)
{
    extern __shared__ char sm[];
    const uint32_t sbase = smem_u32(sm);

    const int t    = threadIdx.x;
    const int lane = t & 31;
    const int warp = t >> 5;
    const int wm   = (warp & 3) * 32;
    const int wn   = (warp >> 2) * 64;
    const int bm   = blockIdx.y * 128;
    const int bn   = blockIdx.x * 128;

    const uint32_t aoffA =
        ((wm + (lane & 15)) * PITCH + ((lane >> 4) * 8)) * 2;
    const uint32_t aoffB =
        ((wn + (lane & 7) + ((lane >> 4) << 3)) * PITCH + (((lane >> 3) & 1) * 8)) * 2;

    float acc[2][8][4];
    #pragma unroll
    for (int mi = 0; mi < 2; mi++)
        #pragma unroll
        for (int j = 0; j < 8; j++)
            #pragma unroll
            for (int q = 0; q < 4; q++) acc[mi][j][q] = 0.0f;

    const int KT = K / 32;

    #define G_ISSUE(kt, stg)                                                  \
        { const uint32_t sb = sbase + (uint32_t)(stg) * STAGEB;               \
          const int row = t >> 1, c = t & 1;                                  \
          const uint32_t d = sb + row * (PITCH * 2) + c * 32;                 \
          const size_t ga = (size_t)(bm + row) * K + (kt) * 32 + c * 16;      \
          const size_t gb = (size_t)(bn + row) * K + (kt) * 32 + c * 16;      \
          cp16(d,              A  + ga);                                      \
          cp16(d + 16,         A  + ga + 8);                                  \
          cp16(d + TILEB,      Bw + gb);                                      \
          cp16(d + TILEB + 16, Bw + gb + 8);                                  \
        }

    G_ISSUE(0, 0); cpcommit();
    G_ISSUE(1, 1); cpcommit();

    int stg = 0;
    for (int kt = 0; kt < KT; kt++) {
        if (kt + 1 < KT) cpwait1(); else cpwait0();
        __syncthreads();

        // early prefetch of kt+2 (wait accounting unchanged: wait precedes issue)
        if (kt + 2 < KT) {
            const int ns = (stg + 2 >= 3) ? stg - 1 : stg + 2;
            G_ISSUE(kt + 2, ns); cpcommit();
        }

        const uint32_t sA = sbase + (uint32_t)stg * STAGEB;
        const uint32_t sB = sA + TILEB;

        #pragma unroll
        for (int ks = 0; ks < 2; ks++) {
            uint32_t af[2][4];
            ldmat4(af[0], sA + aoffA + ks * 32);
            ldmat4(af[1], sA + aoffA + 16 * PITCH * 2 + ks * 32);
            #pragma unroll
            for (int p = 0; p < 4; p++) {
                uint32_t bf4[4];
                ldmat4(bf4, sB + aoffB + p * 16 * PITCH * 2 + ks * 32);
                #pragma unroll
                for (int mi = 0; mi < 2; mi++) {
                    mma16816(acc[mi][2*p],   af[mi], bf4[0], bf4[1]);
                    mma16816(acc[mi][2*p+1], af[mi], bf4[2], bf4[3]);
                }
            }
        }

        stg = (stg + 1 == 3) ? 0 : stg + 1;
    }
    #undef G_ISSUE

    const int r0 = bm + wm + (lane >> 2);
    const int cb = bn + wn + (lane & 3) * 2;
    #pragma unroll
    for (int mi = 0; mi < 2; mi++) {
        #pragma unroll
        for (int j = 0; j < 8; j++) {
            const int col = cb + j * 8;
            const float b0v = bias[col], b1v = bias[col + 1];
            const int ra = r0 + mi * 16, rb = ra + 8;
            float2 v0 = { acc[mi][j][0] + b0v, acc[mi][j][1] + b1v };
            float2 v1 = { acc[mi][j][2] + b0v, acc[mi][j][3] + b1v };
            if (EPI == 1) {
                const float2 ra2 = *reinterpret_cast<const float2*>(
                    res + (size_t)ra * Nn + col);
                const float2 rb2 = *reinterpret_cast<const float2*>(
                    res + (size_t)rb * Nn + col);
                v0.x += ra2.x; v0.y += ra2.y; v1.x += rb2.x; v1.y += rb2.y;
            }
            if (EPI == 2) {
                *reinterpret_cast<uint32_t*>(Ch + (size_t)ra * Nn + col) =
                    pckf(gelu_exact(v0.x), gelu_exact(v0.y));
                *reinterpret_cast<uint32_t*>(Ch + (size_t)rb * Nn + col) =
                    pckf(gelu_exact(v1.x), gelu_exact(v1.y));
            } else if (EPI == 3) {
                *reinterpret_cast<uint32_t*>(Ch + (size_t)ra * Nn + col) =
                    pckf(v0.x, v0.y);
                *reinterpret_cast<uint32_t*>(Ch + (size_t)rb * Nn + col) =
                    pckf(v1.x, v1.y);
            } else {
                *reinterpret_cast<float2*>(Co + (size_t)ra * Nn + col) = v0;
                *reinterpret_cast<float2*>(Co + (size_t)rb * Nn + col) = v1;
            }
        }
    }
}

// ---------------- flash attention v4b: early prefetch ------------------------
#define APITCH 72
#define ATILE  (64 * APITCH * 2)
#define QTILE  (128 * APITCH * 2)
#define ASMEM  (QTILE + 3 * 2 * ATILE)

__global__ __launch_bounds__(256) void flash_attn4_kernel(
    const __half* __restrict__ q, const __half* __restrict__ k,
    const __half* __restrict__ v, __half* __restrict__ o)
{
    extern __shared__ char shm[];
    const uint32_t sbase = smem_u32(shm);
    const uint32_t kvb0  = sbase + QTILE;

    const int t    = threadIdx.x;
    const int lane = t & 31;
    const int warp = t >> 5;
    const int b    = blockIdx.y >> 4;
    const int h    = blockIdx.y & 15;
    const int q0   = blockIdx.x * 128;
    const int wm   = warp * 16;

    #pragma unroll
    for (int i = 0; i < 4; i++) {
        const int idx = i * 256 + t;
        const int row = idx >> 3, c = idx & 7;
        cp16(sbase + row * (APITCH * 2) + c * 16,
             q + (size_t)(b * NSEQ + q0 + row) * CDIM + h * HDIM + c * 8);
    }
    cpcommit();

    #define KV_ISSUE(kt, stg)                                                 \
        { const uint32_t sb = kvb0 + (uint32_t)(stg) * 2 * ATILE;             \
          _Pragma("unroll")                                                   \
          for (int i = 0; i < 2; i++) {                                       \
              const int idx = i * 256 + t;                                    \
              const int row = idx >> 3, c = idx & 7;                          \
              const size_t g = (size_t)(b * NSEQ + (kt) * 64 + row) * CDIM    \
                               + h * HDIM + c * 8;                            \
              const uint32_t d = sb + row * (APITCH * 2) + c * 16;            \
              cp16(d,         k + g);                                        \
              cp16(d + ATILE, v + g);                                        \
          } }

    KV_ISSUE(0, 0); cpcommit();
    KV_ISSUE(1, 1); cpcommit();
    cpwait2();
    __syncthreads();

    uint32_t qf[4][4];
    #pragma unroll
    for (int ks = 0; ks < 4; ks++)
        ldmat4(qf[ks], sbase + ((wm + (lane & 15)) * APITCH + ks * 16
                                + (lane >> 4) * 8) * 2);

    float m0 = -1e30f, m1 = -1e30f, l0 = 0.0f, l1 = 0.0f;
    float oa[8][4];
    #pragma unroll
    for (int j = 0; j < 8; j++)
        #pragma unroll
        for (int p = 0; p < 4; p++) oa[j][p] = 0.0f;

    const uint32_t one2 = 0x3C003C00u;
    const int NT = NSEQ / 64;
    int stg = 0;
    for (int kt = 0; kt < NT; kt++) {
        if (kt + 1 < NT) cpwait1(); else cpwait0();
        __syncthreads();

        // early prefetch of kt+2
        if (kt + 2 < NT) {
            const int ns = (stg + 2 >= 3) ? stg - 1 : stg + 2;
            KV_ISSUE(kt + 2, ns); cpcommit();
        }

        const uint32_t kb = kvb0 + (uint32_t)stg * 2 * ATILE;
        const uint32_t vb = kb + ATILE;

        float sc[8][4];
        #pragma unroll
        for (int j = 0; j < 8; j++)
            #pragma unroll
            for (int p = 0; p < 4; p++) sc[j][p] = 0.0f;

        #pragma unroll
        for (int ks = 0; ks < 4; ks++) {
            #pragma unroll
            for (int p = 0; p < 4; p++) {
                uint32_t r4[4];
                ldmat4(r4, kb + ((p * 16 + (lane & 7) + ((lane >> 4) << 3)) * APITCH
                                 + ks * 16 + ((lane >> 3) & 1) * 8) * 2);
                mma16816(sc[2*p],   qf[ks], r4[0], r4[1]);
                mma16816(sc[2*p+1], qf[ks], r4[2], r4[3]);
            }
        }

        float mx0 = sc[0][0], mx1 = sc[0][2];
        #pragma unroll
        for (int j = 0; j < 8; j++) {
            mx0 = fmaxf(mx0, fmaxf(sc[j][0], sc[j][1]));
            mx1 = fmaxf(mx1, fmaxf(sc[j][2], sc[j][3]));
        }
        mx0 = fmaxf(mx0, __shfl_xor_sync(0xffffffffu, mx0, 1));
        mx0 = fmaxf(mx0, __shfl_xor_sync(0xffffffffu, mx0, 2));
        mx1 = fmaxf(mx1, __shfl_xor_sync(0xffffffffu, mx1, 1));
        mx1 = fmaxf(mx1, __shfl_xor_sync(0xffffffffu, mx1, 2));

        const float mn0 = fmaxf(m0, mx0), mn1 = fmaxf(m1, mx1);
        const float cr0 = ex2f(m0 - mn0), cr1 = ex2f(m1 - mn1);
        m0 = mn0; m1 = mn1;

        uint32_t pf[4][4];
        #pragma unroll
        for (int j = 0; j < 8; j++) {
            const float d0 = sc[j][0] - mn0;
            const float d1 = sc[j][1] - mn0;
            const float d2 = sc[j][2] - mn1;
            const float d3 = sc[j][3] - mn1;
            uint32_t c01, c23;
            asm("cvt.rn.f16x2.f32 %0, %1, %2;" : "=r"(c01) : "f"(d1), "f"(d0));
            asm("cvt.rn.f16x2.f32 %0, %1, %2;" : "=r"(c23) : "f"(d3), "f"(d2));
            uint32_t p01, p23;
            asm("ex2.approx.f16x2 %0, %1;" : "=r"(p01) : "r"(c01));
            asm("ex2.approx.f16x2 %0, %1;" : "=r"(p23) : "r"(c23));
            pf[j >> 1][(j & 1) * 2 + 0] = p01;
            pf[j >> 1][(j & 1) * 2 + 1] = p23;
        }

        float ls[4] = {0.0f, 0.0f, 0.0f, 0.0f};
        #pragma unroll
        for (int ks = 0; ks < 4; ks++) mma16816(ls, pf[ks], one2, one2);
        l0 = l0 * cr0 + ls[0];
        l1 = l1 * cr1 + ls[2];

        #pragma unroll
        for (int j = 0; j < 8; j++) {
            oa[j][0] *= cr0; oa[j][1] *= cr0;
            oa[j][2] *= cr1; oa[j][3] *= cr1;
        }

        #pragma unroll
        for (int ks = 0; ks < 4; ks++) {
            #pragma unroll
            for (int p = 0; p < 4; p++) {
                uint32_t r4[4];
                ldmat4t(r4, vb + ((ks * 16 + (lane & 15)) * APITCH
                                  + p * 16 + ((lane >> 4) << 3)) * 2);
                mma16816(oa[2*p],   pf[ks], r4[0], r4[1]);
                mma16816(oa[2*p+1], pf[ks], r4[2], r4[3]);
            }
        }

        stg = (stg + 1 == 3) ? 0 : stg + 1;
    }
    #undef KV_ISSUE

    const float iv0 = 1.0f / l0, iv1 = 1.0f / l1;
    const int ra = q0 + wm + (lane >> 2);
    const int rb = ra + 8;
    #pragma unroll
    for (int j = 0; j < 8; j++) {
        const int col = h * HDIM + j * 8 + (lane & 3) * 2;
        *reinterpret_cast<uint32_t*>(o + (size_t)(b * NSEQ + ra) * CDIM + col) =
            pckf(oa[j][0] * iv0, oa[j][1] * iv0);
        *reinterpret_cast<uint32_t*>(o + (size_t)(b * NSEQ + rb) * CDIM + col) =
            pckf(oa[j][2] * iv1, oa[j][3] * iv1);
    }
}

// ---------------- host orchestration ----------------------------------------
extern "C" void kernel_launch(void* const* d_in, const int* in_sizes, int n_in,
                              void* d_out, int out_size)
{
    const float* x      = (const float*)d_in[0];
    const float* wq     = (const float*)d_in[1];
    const float* bq     = (const float*)d_in[2];
    const float* wk     = (const float*)d_in[3];
    const float* bk     = (const float*)d_in[4];
    const float* wv     = (const float*)d_in[5];
    const float* bv     = (const float*)d_in[6];
    const float* wo     = (const float*)d_in[7];
    const float* bo     = (const float*)d_in[8];
    const float* scale1 = (const float*)d_in[9];
    const float* scale2 = (const float*)d_in[10];
    const float* w1     = (const float*)d_in[11];
    const float* b1     = (const float*)d_in[12];
    const float* w2     = (const float*)d_in[13];
    const float* b2     = (const float*)d_in[14];
    float* out = (float*)d_out;

    __half *p_xn, *p_qkvh, *p_qb, *p_kb, *p_vb, *p_ctx, *p_xn2, *p_h;
    __half *p_wqkv, *p_wo, *p_w1, *p_w2;
    float *p_x2, *p_bqkv;
    cudaGetSymbolAddress((void**)&p_xn,   g_xn);
    cudaGetSymbolAddress((void**)&p_qkvh, g_qkvh);
    cudaGetSymbolAddress((void**)&p_qb,   g_qb);
    cudaGetSymbolAddress((void**)&p_kb,   g_kb);
    cudaGetSymbolAddress((void**)&p_vb,   g_vb);
    cudaGetSymbolAddress((void**)&p_ctx,  g_ctx);
    cudaGetSymbolAddress((void**)&p_x2,   g_x2);
    cudaGetSymbolAddress((void**)&p_xn2,  g_xn2);
    cudaGetSymbolAddress((void**)&p_h,    g_h);
    cudaGetSymbolAddress((void**)&p_wqkv, g_wqkv);
    cudaGetSymbolAddress((void**)&p_wo,   g_wo);
    cudaGetSymbolAddress((void**)&p_w1,   g_w1);
    cudaGetSymbolAddress((void**)&p_w2,   g_w2);
    cudaGetSymbolAddress((void**)&p_bqkv, g_bqkv);

    cudaFuncSetAttribute(gemm4_kernel<0>,
                         cudaFuncAttributeMaxDynamicSharedMemorySize, GSMEM);
    cudaFuncSetAttribute(gemm4_kernel<1>,
                         cudaFuncAttributeMaxDynamicSharedMemorySize, GSMEM);
    cudaFuncSetAttribute(gemm4_kernel<2>,
                         cudaFuncAttributeMaxDynamicSharedMemorySize, GSMEM);
    cudaFuncSetAttribute(gemm4_kernel<3>,
                         cudaFuncAttributeMaxDynamicSharedMemorySize, GSMEM);
    cudaFuncSetAttribute(flash_attn4_kernel,
                         cudaFuncAttributeMaxDynamicSharedMemorySize, ASMEM);

    const dim3 tb(32, 8);

    bias_concat_kernel<<<QKVN / 256, 256>>>(bq, bk, bv, p_bqkv);
    transpose_h2_kernel<<<dim3(CDIM/64, CDIM/64), tb>>>(wq, p_wqkv, CDIM, CDIM);
    transpose_h2_kernel<<<dim3(CDIM/64, CDIM/64), tb>>>(
        wk, p_wqkv + (size_t)CDIM*CDIM, CDIM, CDIM);
    transpose_h2_kernel<<<dim3(CDIM/64, CDIM/64), tb>>>(
        wv, p_wqkv + (size_t)2*CDIM*CDIM, CDIM, CDIM);
    rmsnorm_h_kernel<<<MTOT, 256>>>(x, scale1, p_xn);
    // fused QKV GEMM -> fp16
    gemm4_kernel<3><<<dim3(QKVN/128, MTOT/128), 256, GSMEM>>>(
        p_xn, p_wqkv, p_bqkv, nullptr, nullptr, p_qkvh, MTOT, QKVN, CDIM);
    postqkv_kernel<<<dim3(MTOT*NHEAD*4/256, 3), 256>>>(p_qkvh, p_qb, p_kb, p_vb);
    flash_attn4_kernel<<<dim3(NSEQ/128, 2*NHEAD), 256, ASMEM>>>(
        p_qb, p_kb, p_vb, p_ctx);
    transpose_h2_kernel<<<dim3(CDIM/64, CDIM/64), tb>>>(wo, p_wo, CDIM, CDIM);
    gemm4_kernel<1><<<dim3(CDIM/128, MTOT/128), 256, GSMEM>>>(
        p_ctx, p_wo, bo, x, p_x2, nullptr, MTOT, CDIM, CDIM);
    rmsnorm_h_kernel<<<MTOT, 256>>>(p_x2, scale2, p_xn2);
    transpose_h2_kernel<<<dim3(FFDIM/64, CDIM/64), tb>>>(w1, p_w1, CDIM, FFDIM);
    gemm4_kernel<2><<<dim3(FFDIM/128, MTOT/128), 256, GSMEM>>>(
        p_xn2, p_w1, b1, nullptr, nullptr, p_h, MTOT, FFDIM, CDIM);
    transpose_h2_kernel<<<dim3(CDIM/64, FFDIM/64), tb>>>(w2, p_w2, FFDIM, CDIM);
    gemm4_kernel<1><<<dim3(CDIM/128, MTOT/128), 256, GSMEM>>>(
        p_h, p_w2, b2, p_x2, out, nullptr, MTOT, CDIM, FFDIM);
}

// round 12
// speedup vs baseline: 1.0983x; 1.0983x over previous
#include <cuda_runtime.h>
#include <cuda_fp16.h>
#include <math.h>
#include <stdint.h>

// Problem dims (fixed): B=2, N=2048, C=1024, H=16, D=64, FF=4096
#define MTOT 4096
#define CDIM 1024
#define FFDIM 4096
#define NSEQ 2048
#define NHEAD 16
#define HDIM 64
#define QKVN 3072

// ---------------- scratch (no allocations -> __device__ globals) ------------
__device__ __half g_xn  [MTOT*CDIM];
__device__ __half g_qb  [MTOT*CDIM], g_kb[MTOT*CDIM], g_vb[MTOT*CDIM];
__device__ __half g_ctx [MTOT*CDIM];
__device__ float  g_x2  [MTOT*CDIM];
__device__ __half g_xn2 [MTOT*CDIM];
__device__ __half g_h   [MTOT*FFDIM];
__device__ __half g_wqkv[QKVN*CDIM];
__device__ __half g_wo  [CDIM*CDIM];
__device__ __half g_w1  [FFDIM*CDIM];
__device__ __half g_w2  [CDIM*FFDIM];
__device__ float  g_bqkv[QKVN];

// ---------------- helpers ----------------------------------------------------
__device__ __forceinline__ uint32_t smem_u32(const void* p) {
    uint32_t a;
    asm("{ .reg .u64 t; cvta.to.shared.u64 t, %1; cvt.u32.u64 %0, t; }"
        : "=r"(a) : "l"(p));
    return a;
}
__device__ __forceinline__ void ldmat4(uint32_t (&r)[4], uint32_t addr) {
    asm volatile("ldmatrix.sync.aligned.m8n8.x4.shared.b16 {%0,%1,%2,%3}, [%4];"
                 : "=r"(r[0]), "=r"(r[1]), "=r"(r[2]), "=r"(r[3]) : "r"(addr));
}
__device__ __forceinline__ void ldmat4t(uint32_t (&r)[4], uint32_t addr) {
    asm volatile("ldmatrix.sync.aligned.m8n8.x4.trans.shared.b16 {%0,%1,%2,%3}, [%4];"
                 : "=r"(r[0]), "=r"(r[1]), "=r"(r[2]), "=r"(r[3]) : "r"(addr));
}
__device__ __forceinline__ void mma16816(float (&d)[4], const uint32_t (&a)[4],
                                         uint32_t b0, uint32_t b1) {
    asm volatile(
        "mma.sync.aligned.m16n8k16.row.col.f32.f16.f16.f32 "
        "{%0,%1,%2,%3}, {%4,%5,%6,%7}, {%8,%9}, {%0,%1,%2,%3};"
        : "+f"(d[0]), "+f"(d[1]), "+f"(d[2]), "+f"(d[3])
        : "r"(a[0]), "r"(a[1]), "r"(a[2]), "r"(a[3]), "r"(b0), "r"(b1));
}
__device__ __forceinline__ uint32_t pckh(__half a, __half b) {
    __half2 t(a, b);
    return *reinterpret_cast<uint32_t*>(&t);
}
__device__ __forceinline__ uint32_t pckf(float a, float b) {
    return pckh(__float2half(a), __float2half(b));
}
__device__ __forceinline__ float ex2f(float x) {
    float y;
    asm("ex2.approx.f32 %0, %1;" : "=f"(y) : "f"(x));
    return y;
}
__device__ __forceinline__ float gelu_exact(float x) {
    return 0.5f * x * (1.0f + erff(x * 0.7071067811865476f));
}
__device__ __forceinline__ void cp16(uint32_t d, const void* s) {
    asm volatile("cp.async.cg.shared.global [%0], [%1], 16;" :: "r"(d), "l"(s));
}
__device__ __forceinline__ void cpcommit() {
    asm volatile("cp.async.commit_group;" ::: "memory");
}
__device__ __forceinline__ void cpwait0() {
    asm volatile("cp.async.wait_group 0;" ::: "memory");
}
__device__ __forceinline__ void cpwait1() {
    asm volatile("cp.async.wait_group 1;" ::: "memory");
}
__device__ __forceinline__ void cpwait2() {
    asm volatile("cp.async.wait_group 2;" ::: "memory");
}

// ---------------- misc small kernels (R10 versions) --------------------------
__global__ void bias_concat_kernel(const float* bq, const float* bk,
                                   const float* bv, float* out)
{
    const int i = blockIdx.x * 256 + threadIdx.x;
    float v;
    if (i < 1024)      v = bq[i];
    else if (i < 2048) v = bk[i - 1024];
    else               v = bv[i - 2048];
    out[i] = v;
}

__global__ __launch_bounds__(256) void transpose_h_kernel(
    const float* __restrict__ in, __half* __restrict__ o, int R, int Cc)
{
    __shared__ float ts[32][33];
    const int tx = threadIdx.x, ty = threadIdx.y;
    const int c0 = blockIdx.x * 32, r0 = blockIdx.y * 32;
    #pragma unroll
    for (int i = 0; i < 4; i++)
        ts[ty + 8*i][tx] = in[(size_t)(r0 + ty + 8*i) * Cc + c0 + tx];
    __syncthreads();
    #pragma unroll
    for (int i = 0; i < 4; i++)
        o[(size_t)(c0 + ty + 8*i) * R + r0 + tx] = __float2half(ts[tx][ty + 8*i]);
}

__global__ __launch_bounds__(256) void rmsnorm_h_kernel(
    const float* __restrict__ x, const float* __restrict__ scale,
    __half* __restrict__ o)
{
    __shared__ float red[8];
    const int row = blockIdx.x;
    const int t   = threadIdx.x;
    const float* xr = x + (size_t)row * CDIM;

    float4 v = *reinterpret_cast<const float4*>(xr + t * 4);
    float ss = v.x * v.x + v.y * v.y + v.z * v.z + v.w * v.w;
    #pragma unroll
    for (int of = 16; of > 0; of >>= 1) ss += __shfl_xor_sync(0xffffffffu, ss, of);
    if ((t & 31) == 0) red[t >> 5] = ss;
    __syncthreads();
    if (t < 8) {
        float s2 = red[t];
        #pragma unroll
        for (int of = 4; of > 0; of >>= 1) s2 += __shfl_xor_sync(0xffu, s2, of);
        if (t == 0) red[0] = s2;
    }
    __syncthreads();
    const float norm = sqrtf(red[0]);
    const float inv  = 1.0f / (norm * 0.03125f + 1e-8f);

    float4 sc = *reinterpret_cast<const float4*>(scale + t * 4);
    uint2 w;
    w.x = pckf(v.x * sc.x * inv, v.y * sc.y * inv);
    w.y = pckf(v.z * sc.z * inv, v.w * sc.w * inv);
    *reinterpret_cast<uint2*>(o + (size_t)row * CDIM + t * 4) = w;
}

// ---------------- GEMM v4 (R10 verbatim) + EPI 4 = fused QKV rotary ---------
// EPI: 0 bias->fp32 ; 1 bias+res->fp32 ; 2 bias+gelu->fp16 ; 3 bias->fp16 ;
//      4 bias + rotary/scale + scatter to q/k/v (fp16)
#define PITCH 40
#define TILEB (128 * PITCH * 2)     // 10240 B
#define STAGEB (2 * TILEB)          // 20480 B (A + B)
#define GSMEM (3 * STAGEB)          // 61440 B

template <int EPI>
__global__ __launch_bounds__(256, 2) void gemm4_kernel(
    const __half* __restrict__ A, const __half* __restrict__ Bw,
    const float* __restrict__ bias, const float* __restrict__ res,
    float* __restrict__ Co, __half* __restrict__ Ch,
    __half* __restrict__ Qd, __half* __restrict__ Kd, __half* __restrict__ Vd,
    int M, int Nn, int K)
{
    extern __shared__ char sm[];
    const uint32_t sbase = smem_u32(sm);

    const int t    = threadIdx.x;
    const int lane = t & 31;
    const int warp = t >> 5;
    const int wm   = (warp & 3) * 32;
    const int wn   = (warp >> 2) * 64;
    const int bm   = blockIdx.y * 128;
    const int bn   = blockIdx.x * 128;

    const uint32_t aoffA =
        ((wm + (lane & 15)) * PITCH + ((lane >> 4) * 8)) * 2;
    const uint32_t aoffB =
        ((wn + (lane & 7) + ((lane >> 4) << 3)) * PITCH + (((lane >> 3) & 1) * 8)) * 2;

    float acc[2][8][4];
    #pragma unroll
    for (int mi = 0; mi < 2; mi++)
        #pragma unroll
        for (int j = 0; j < 8; j++)
            #pragma unroll
            for (int q = 0; q < 4; q++) acc[mi][j][q] = 0.0f;

    const int KT = K / 32;

    #define G_ISSUE(kt, stg)                                                  \
        { const uint32_t sb = sbase + (uint32_t)(stg) * STAGEB;               \
          const int row = t >> 1, c = t & 1;                                  \
          const uint32_t d = sb + row * (PITCH * 2) + c * 32;                 \
          const size_t ga = (size_t)(bm + row) * K + (kt) * 32 + c * 16;      \
          const size_t gb = (size_t)(bn + row) * K + (kt) * 32 + c * 16;      \
          cp16(d,              A  + ga);                                      \
          cp16(d + 16,         A  + ga + 8);                                  \
          cp16(d + TILEB,      Bw + gb);                                      \
          cp16(d + TILEB + 16, Bw + gb + 8);                                  \
        }

    G_ISSUE(0, 0); cpcommit();
    G_ISSUE(1, 1); cpcommit();

    int stg = 0;
    for (int kt = 0; kt < KT; kt++) {
        if (kt + 1 < KT) cpwait1(); else cpwait0();
        __syncthreads();

        const uint32_t sA = sbase + (uint32_t)stg * STAGEB;
        const uint32_t sB = sA + TILEB;

        #pragma unroll
        for (int ks = 0; ks < 2; ks++) {
            uint32_t af[2][4];
            ldmat4(af[0], sA + aoffA + ks * 32);
            ldmat4(af[1], sA + aoffA + 16 * PITCH * 2 + ks * 32);
            #pragma unroll
            for (int p = 0; p < 4; p++) {
                uint32_t bf4[4];
                ldmat4(bf4, sB + aoffB + p * 16 * PITCH * 2 + ks * 32);
                #pragma unroll
                for (int mi = 0; mi < 2; mi++) {
                    mma16816(acc[mi][2*p],   af[mi], bf4[0], bf4[1]);
                    mma16816(acc[mi][2*p+1], af[mi], bf4[2], bf4[3]);
                }
            }
        }

        if (kt + 2 < KT) {
            const int ns = (stg + 2 >= 3) ? stg - 1 : stg + 2;
            G_ISSUE(kt + 2, ns); cpcommit();
        }
        stg = (stg + 1 == 3) ? 0 : stg + 1;
    }
    #undef G_ISSUE

    const int r0 = bm + wm + (lane >> 2);
    const int cb = bn + wn + (lane & 3) * 2;

    if (EPI == 4) {
        // warp tile N (64) == head dim: rotary is intra-warp.
        const float cscale = 0.125f * 1.4426950408889634f;
        const int secc    = (bn + wn) >> 10;                 // 0=q 1=k 2=v
        __half* dst = (secc == 0) ? Qd : (secc == 1) ? Kd : Vd;
        const int colbase = ((bn + wn) & 1023) + (lane & 3) * 2;
        const int srcl    = (lane & ~3) | ((lane + 3) & 3);
        const int q4      = lane & 3;
        #pragma unroll
        for (int mi = 0; mi < 2; mi++) {
            float a0[8], a1[8], c0[8], c1[8];
            #pragma unroll
            for (int j = 0; j < 8; j++) {
                const int col = cb + j * 8;
                const float b0v = bias[col], b1v = bias[col + 1];
                a0[j] = acc[mi][j][0] + b0v;
                a1[j] = acc[mi][j][1] + b1v;
                c0[j] = acc[mi][j][2] + b0v;
                c1[j] = acc[mi][j][3] + b1v;
            }
            const int ra = r0 + mi * 16, rb = ra + 8;
            if (secc == 2) {
                #pragma unroll
                for (int j = 0; j < 8; j++) {
                    const int cc = colbase + j * 8;
                    *reinterpret_cast<uint32_t*>(dst + (size_t)ra * CDIM + cc) =
                        pckf(a0[j], a1[j]);
                    *reinterpret_cast<uint32_t*>(dst + (size_t)rb * CDIM + cc) =
                        pckf(c0[j], c1[j]);
                }
            } else {
                float pa[8], pc[8];
                #pragma unroll
                for (int j = 0; j < 8; j++) {
                    pa[j] = __shfl_sync(0xffffffffu, a1[j], srcl);
                    pc[j] = __shfl_sync(0xffffffffu, c1[j], srcl);
                }
                #pragma unroll
                for (int j = 0; j < 8; j++) {
                    const float prevA = q4 ? pa[j] : pa[(j + 7) & 7];
                    const float prevC = q4 ? pc[j] : pc[(j + 7) & 7];
                    float oA0 = a0[j] - prevA, oA1 = a1[j] - a0[j];
                    float oC0 = c0[j] - prevC, oC1 = c1[j] - c0[j];
                    if (secc == 0) {
                        oA0 *= cscale; oA1 *= cscale;
                        oC0 *= cscale; oC1 *= cscale;
                    }
                    const int cc = colbase + j * 8;
                    *reinterpret_cast<uint32_t*>(dst + (size_t)ra * CDIM + cc) =
                        pckf(oA0, oA1);
                    *reinterpret_cast<uint32_t*>(dst + (size_t)rb * CDIM + cc) =
                        pckf(oC0, oC1);
                }
            }
        }
        return;
    }

    #pragma unroll
    for (int mi = 0; mi < 2; mi++) {
        #pragma unroll
        for (int j = 0; j < 8; j++) {
            const int col = cb + j * 8;
            const float b0v = bias[col], b1v = bias[col + 1];
            const int ra = r0 + mi * 16, rb = ra + 8;
            float2 v0 = { acc[mi][j][0] + b0v, acc[mi][j][1] + b1v };
            float2 v1 = { acc[mi][j][2] + b0v, acc[mi][j][3] + b1v };
            if (EPI == 1) {
                const float2 ra2 = *reinterpret_cast<const float2*>(
                    res + (size_t)ra * Nn + col);
                const float2 rb2 = *reinterpret_cast<const float2*>(
                    res + (size_t)rb * Nn + col);
                v0.x += ra2.x; v0.y += ra2.y; v1.x += rb2.x; v1.y += rb2.y;
            }
            if (EPI == 2) {
                *reinterpret_cast<uint32_t*>(Ch + (size_t)ra * Nn + col) =
                    pckf(gelu_exact(v0.x), gelu_exact(v0.y));
                *reinterpret_cast<uint32_t*>(Ch + (size_t)rb * Nn + col) =
                    pckf(gelu_exact(v1.x), gelu_exact(v1.y));
            } else if (EPI == 3) {
                *reinterpret_cast<uint32_t*>(Ch + (size_t)ra * Nn + col) =
                    pckf(v0.x, v0.y);
                *reinterpret_cast<uint32_t*>(Ch + (size_t)rb * Nn + col) =
                    pckf(v1.x, v1.y);
            } else {
                *reinterpret_cast<float2*>(Co + (size_t)ra * Nn + col) = v0;
                *reinterpret_cast<float2*>(Co + (size_t)rb * Nn + col) = v1;
            }
        }
    }
}

// ---------------- flash attention v4 (R10 verbatim) --------------------------
#define APITCH 72
#define ATILE  (64 * APITCH * 2)
#define QTILE  (128 * APITCH * 2)
#define ASMEM  (QTILE + 3 * 2 * ATILE)

__global__ __launch_bounds__(256) void flash_attn4_kernel(
    const __half* __restrict__ q, const __half* __restrict__ k,
    const __half* __restrict__ v, __half* __restrict__ o)
{
    extern __shared__ char shm[];
    const uint32_t sbase = smem_u32(shm);
    const uint32_t kvb0  = sbase + QTILE;

    const int t    = threadIdx.x;
    const int lane = t & 31;
    const int warp = t >> 5;
    const int b    = blockIdx.y >> 4;
    const int h    = blockIdx.y & 15;
    const int q0   = blockIdx.x * 128;
    const int wm   = warp * 16;

    #pragma unroll
    for (int i = 0; i < 4; i++) {
        const int idx = i * 256 + t;
        const int row = idx >> 3, c = idx & 7;
        cp16(sbase + row * (APITCH * 2) + c * 16,
             q + (size_t)(b * NSEQ + q0 + row) * CDIM + h * HDIM + c * 8);
    }
    cpcommit();

    #define KV_ISSUE(kt, stg)                                                 \
        { const uint32_t sb = kvb0 + (uint32_t)(stg) * 2 * ATILE;             \
          _Pragma("unroll")                                                   \
          for (int i = 0; i < 2; i++) {                                       \
              const int idx = i * 256 + t;                                    \
              const int row = idx >> 3, c = idx & 7;                          \
              const size_t g = (size_t)(b * NSEQ + (kt) * 64 + row) * CDIM    \
                               + h * HDIM + c * 8;                            \
              const uint32_t d = sb + row * (APITCH * 2) + c * 16;            \
              cp16(d,         k + g);                                        \
              cp16(d + ATILE, v + g);                                        \
          } }

    KV_ISSUE(0, 0); cpcommit();
    KV_ISSUE(1, 1); cpcommit();
    cpwait2();
    __syncthreads();

    uint32_t qf[4][4];
    #pragma unroll
    for (int ks = 0; ks < 4; ks++)
        ldmat4(qf[ks], sbase + ((wm + (lane & 15)) * APITCH + ks * 16
                                + (lane >> 4) * 8) * 2);

    float m0 = -1e30f, m1 = -1e30f, l0 = 0.0f, l1 = 0.0f;
    float oa[8][4];
    #pragma unroll
    for (int j = 0; j < 8; j++)
        #pragma unroll
        for (int p = 0; p < 4; p++) oa[j][p] = 0.0f;

    const uint32_t one2 = 0x3C003C00u;
    const int NT = NSEQ / 64;
    int stg = 0;
    for (int kt = 0; kt < NT; kt++) {
        if (kt + 1 < NT) cpwait1(); else cpwait0();
        __syncthreads();

        const uint32_t kb = kvb0 + (uint32_t)stg * 2 * ATILE;
        const uint32_t vb = kb + ATILE;

        float sc[8][4];
        #pragma unroll
        for (int j = 0; j < 8; j++)
            #pragma unroll
            for (int p = 0; p < 4; p++) sc[j][p] = 0.0f;

        #pragma unroll
        for (int ks = 0; ks < 4; ks++) {
            #pragma unroll
            for (int p = 0; p < 4; p++) {
                uint32_t r4[4];
                ldmat4(r4, kb + ((p * 16 + (lane & 7) + ((lane >> 4) << 3)) * APITCH
                                 + ks * 16 + ((lane >> 3) & 1) * 8) * 2);
                mma16816(sc[2*p],   qf[ks], r4[0], r4[1]);
                mma16816(sc[2*p+1], qf[ks], r4[2], r4[3]);
            }
        }

        float mx0 = sc[0][0], mx1 = sc[0][2];
        #pragma unroll
        for (int j = 0; j < 8; j++) {
            mx0 = fmaxf(mx0, fmaxf(sc[j][0], sc[j][1]));
            mx1 = fmaxf(mx1, fmaxf(sc[j][2], sc[j][3]));
        }
        mx0 = fmaxf(mx0, __shfl_xor_sync(0xffffffffu, mx0, 1));
        mx0 = fmaxf(mx0, __shfl_xor_sync(0xffffffffu, mx0, 2));
        mx1 = fmaxf(mx1, __shfl_xor_sync(0xffffffffu, mx1, 1));
        mx1 = fmaxf(mx1, __shfl_xor_sync(0xffffffffu, mx1, 2));

        const float mn0 = fmaxf(m0, mx0), mn1 = fmaxf(m1, mx1);
        const float cr0 = ex2f(m0 - mn0), cr1 = ex2f(m1 - mn1);
        m0 = mn0; m1 = mn1;

        uint32_t pf[4][4];
        #pragma unroll
        for (int j = 0; j < 8; j++) {
            const float d0 = sc[j][0] - mn0;
            const float d1 = sc[j][1] - mn0;
            const float d2 = sc[j][2] - mn1;
            const float d3 = sc[j][3] - mn1;
            uint32_t c01, c23;
            asm("cvt.rn.f16x2.f32 %0, %1, %2;" : "=r"(c01) : "f"(d1), "f"(d0));
            asm("cvt.rn.f16x2.f32 %0, %1, %2;" : "=r"(c23) : "f"(d3), "f"(d2));
            uint32_t p01, p23;
            asm("ex2.approx.f16x2 %0, %1;" : "=r"(p01) : "r"(c01));
            asm("ex2.approx.f16x2 %0, %1;" : "=r"(p23) : "r"(c23));
            pf[j >> 1][(j & 1) * 2 + 0] = p01;
            pf[j >> 1][(j & 1) * 2 + 1] = p23;
        }

        float ls[4] = {0.0f, 0.0f, 0.0f, 0.0f};
        #pragma unroll
        for (int ks = 0; ks < 4; ks++) mma16816(ls, pf[ks], one2, one2);
        l0 = l0 * cr0 + ls[0];
        l1 = l1 * cr1 + ls[2];

        #pragma unroll
        for (int j = 0; j < 8; j++) {
            oa[j][0] *= cr0; oa[j][1] *= cr0;
            oa[j][2] *= cr1; oa[j][3] *= cr1;
        }

        #pragma unroll
        for (int ks = 0; ks < 4; ks++) {
            #pragma unroll
            for (int p = 0; p < 4; p++) {
                uint32_t r4[4];
                ldmat4t(r4, vb + ((ks * 16 + (lane & 15)) * APITCH
                                  + p * 16 + ((lane >> 4) << 3)) * 2);
                mma16816(oa[2*p],   pf[ks], r4[0], r4[1]);
                mma16816(oa[2*p+1], pf[ks], r4[2], r4[3]);
            }
        }

        if (kt + 2 < NT) {
            const int ns = (stg + 2 >= 3) ? stg - 1 : stg + 2;
            KV_ISSUE(kt + 2, ns); cpcommit();
        }
        stg = (stg + 1 == 3) ? 0 : stg + 1;
    }
    #undef KV_ISSUE

    const float iv0 = 1.0f / l0, iv1 = 1.0f / l1;
    const int ra = q0 + wm + (lane >> 2);
    const int rb = ra + 8;
    #pragma unroll
    for (int j = 0; j < 8; j++) {
        const int col = h * HDIM + j * 8 + (lane & 3) * 2;
        *reinterpret_cast<uint32_t*>(o + (size_t)(b * NSEQ + ra) * CDIM + col) =
            pckf(oa[j][0] * iv0, oa[j][1] * iv0);
        *reinterpret_cast<uint32_t*>(o + (size_t)(b * NSEQ + rb) * CDIM + col) =
            pckf(oa[j][2] * iv1, oa[j][3] * iv1);
    }
}

// ---------------- host orchestration ----------------------------------------
extern "C" void kernel_launch(void* const* d_in, const int* in_sizes, int n_in,
                              void* d_out, int out_size)
{
    const float* x      = (const float*)d_in[0];
    const float* wq     = (const float*)d_in[1];
    const float* bq     = (const float*)d_in[2];
    const float* wk     = (const float*)d_in[3];
    const float* bk     = (const float*)d_in[4];
    const float* wv     = (const float*)d_in[5];
    const float* bv     = (const float*)d_in[6];
    const float* wo     = (const float*)d_in[7];
    const float* bo     = (const float*)d_in[8];
    const float* scale1 = (const float*)d_in[9];
    const float* scale2 = (const float*)d_in[10];
    const float* w1     = (const float*)d_in[11];
    const float* b1     = (const float*)d_in[12];
    const float* w2     = (const float*)d_in[13];
    const float* b2     = (const float*)d_in[14];
    float* out = (float*)d_out;

    __half *p_xn, *p_qb, *p_kb, *p_vb, *p_ctx, *p_xn2, *p_h;
    __half *p_wqkv, *p_wo, *p_w1, *p_w2;
    float *p_x2, *p_bqkv;
    cudaGetSymbolAddress((void**)&p_xn,   g_xn);
    cudaGetSymbolAddress((void**)&p_qb,   g_qb);
    cudaGetSymbolAddress((void**)&p_kb,   g_kb);
    cudaGetSymbolAddress((void**)&p_vb,   g_vb);
    cudaGetSymbolAddress((void**)&p_ctx,  g_ctx);
    cudaGetSymbolAddress((void**)&p_x2,   g_x2);
    cudaGetSymbolAddress((void**)&p_xn2,  g_xn2);
    cudaGetSymbolAddress((void**)&p_h,    g_h);
    cudaGetSymbolAddress((void**)&p_wqkv, g_wqkv);
    cudaGetSymbolAddress((void**)&p_wo,   g_wo);
    cudaGetSymbolAddress((void**)&p_w1,   g_w1);
    cudaGetSymbolAddress((void**)&p_w2,   g_w2);
    cudaGetSymbolAddress((void**)&p_bqkv, g_bqkv);

    cudaFuncSetAttribute(gemm4_kernel<0>,
                         cudaFuncAttributeMaxDynamicSharedMemorySize, GSMEM);
    cudaFuncSetAttribute(gemm4_kernel<1>,
                         cudaFuncAttributeMaxDynamicSharedMemorySize, GSMEM);
    cudaFuncSetAttribute(gemm4_kernel<2>,
                         cudaFuncAttributeMaxDynamicSharedMemorySize, GSMEM);
    cudaFuncSetAttribute(gemm4_kernel<4>,
                         cudaFuncAttributeMaxDynamicSharedMemorySize, GSMEM);
    cudaFuncSetAttribute(flash_attn4_kernel,
                         cudaFuncAttributeMaxDynamicSharedMemorySize, ASMEM);

    const dim3 tb(32, 8);

    bias_concat_kernel<<<QKVN / 256, 256>>>(bq, bk, bv, p_bqkv);
    transpose_h_kernel<<<dim3(CDIM/32, CDIM/32), tb>>>(wq, p_wqkv, CDIM, CDIM);
    transpose_h_kernel<<<dim3(CDIM/32, CDIM/32), tb>>>(
        wk, p_wqkv + (size_t)CDIM*CDIM, CDIM, CDIM);
    transpose_h_kernel<<<dim3(CDIM/32, CDIM/32), tb>>>(
        wv, p_wqkv + (size_t)2*CDIM*CDIM, CDIM, CDIM);
    rmsnorm_h_kernel<<<MTOT, 256>>>(x, scale1, p_xn);
    // fused QKV GEMM with rotary/scale/scatter epilogue
    gemm4_kernel<4><<<dim3(QKVN/128, MTOT/128), 256, GSMEM>>>(
        p_xn, p_wqkv, p_bqkv, nullptr, nullptr, nullptr,
        p_qb, p_kb, p_vb, MTOT, QKVN, CDIM);
    flash_attn4_kernel<<<dim3(NSEQ/128, 2*NHEAD), 256, ASMEM>>>(
        p_qb, p_kb, p_vb, p_ctx);
    transpose_h_kernel<<<dim3(CDIM/32, CDIM/32), tb>>>(wo, p_wo, CDIM, CDIM);
    gemm4_kernel<1><<<dim3(CDIM/128, MTOT/128), 256, GSMEM>>>(
        p_ctx, p_wo, bo, x, p_x2, nullptr,
        nullptr, nullptr, nullptr, MTOT, CDIM, CDIM);
    rmsnorm_h_kernel<<<MTOT, 256>>>(p_x2, scale2, p_xn2);
    transpose_h_kernel<<<dim3(FFDIM/32, CDIM/32), tb>>>(w1, p_w1, CDIM, FFDIM);
    gemm4_kernel<2><<<dim3(FFDIM/128, MTOT/128), 256, GSMEM>>>(
        p_xn2, p_w1, b1, nullptr, nullptr, p_h,
        nullptr, nullptr, nullptr, MTOT, FFDIM, CDIM);
    transpose_h_kernel<<<dim3(CDIM/32, FFDIM/32), tb>>>(w2, p_w2, FFDIM, CDIM);
    gemm4_kernel<1><<<dim3(CDIM/128, MTOT/128), 256, GSMEM>>>(
        p_h, p_w2, b2, p_x2, out, nullptr,
        nullptr, nullptr, nullptr, MTOT, CDIM, FFDIM);
}

// round 13
// speedup vs baseline: 1.1026x; 1.0039x over previous
#include <cuda_runtime.h>
#include <cuda_fp16.h>
#include <math.h>
#include <stdint.h>

// Problem dims (fixed): B=2, N=2048, C=1024, H=16, D=64, FF=4096
#define MTOT 4096
#define CDIM 1024
#define FFDIM 4096
#define NSEQ 2048
#define NHEAD 16
#define HDIM 64
#define QKVN 3072

// ---------------- scratch (no allocations -> __device__ globals) ------------
__device__ __half g_xn  [MTOT*CDIM];
__device__ __half g_qb  [MTOT*CDIM], g_kb[MTOT*CDIM], g_vb[MTOT*CDIM];
__device__ __half g_ctx [MTOT*CDIM];
__device__ float  g_x2  [MTOT*CDIM];
__device__ __half g_xn2 [MTOT*CDIM];
__device__ __half g_h   [MTOT*FFDIM];
__device__ __half g_wqkv[QKVN*CDIM];
__device__ __half g_wo  [CDIM*CDIM];
__device__ __half g_w1  [FFDIM*CDIM];
__device__ __half g_w2  [CDIM*FFDIM];
__device__ float  g_bqkv[QKVN];

// ---------------- helpers ----------------------------------------------------
__device__ __forceinline__ uint32_t smem_u32(const void* p) {
    uint32_t a;
    asm("{ .reg .u64 t; cvta.to.shared.u64 t, %1; cvt.u32.u64 %0, t; }"
        : "=r"(a) : "l"(p));
    return a;
}
__device__ __forceinline__ void ldmat4(uint32_t (&r)[4], uint32_t addr) {
    asm volatile("ldmatrix.sync.aligned.m8n8.x4.shared.b16 {%0,%1,%2,%3}, [%4];"
                 : "=r"(r[0]), "=r"(r[1]), "=r"(r[2]), "=r"(r[3]) : "r"(addr));
}
__device__ __forceinline__ void ldmat4t(uint32_t (&r)[4], uint32_t addr) {
    asm volatile("ldmatrix.sync.aligned.m8n8.x4.trans.shared.b16 {%0,%1,%2,%3}, [%4];"
                 : "=r"(r[0]), "=r"(r[1]), "=r"(r[2]), "=r"(r[3]) : "r"(addr));
}
__device__ __forceinline__ void mma16816(float (&d)[4], const uint32_t (&a)[4],
                                         uint32_t b0, uint32_t b1) {
    asm volatile(
        "mma.sync.aligned.m16n8k16.row.col.f32.f16.f16.f32 "
        "{%0,%1,%2,%3}, {%4,%5,%6,%7}, {%8,%9}, {%0,%1,%2,%3};"
        : "+f"(d[0]), "+f"(d[1]), "+f"(d[2]), "+f"(d[3])
        : "r"(a[0]), "r"(a[1]), "r"(a[2]), "r"(a[3]), "r"(b0), "r"(b1));
}
__device__ __forceinline__ uint32_t pckh(__half a, __half b) {
    __half2 t(a, b);
    return *reinterpret_cast<uint32_t*>(&t);
}
__device__ __forceinline__ uint32_t pckf(float a, float b) {
    return pckh(__float2half(a), __float2half(b));
}
__device__ __forceinline__ float ex2f(float x) {
    float y;
    asm("ex2.approx.f32 %0, %1;" : "=f"(y) : "f"(x));
    return y;
}
__device__ __forceinline__ float gelu_exact(float x) {
    return 0.5f * x * (1.0f + erff(x * 0.7071067811865476f));
}
__device__ __forceinline__ void cp16(uint32_t d, const void* s) {
    asm volatile("cp.async.cg.shared.global [%0], [%1], 16;" :: "r"(d), "l"(s));
}
__device__ __forceinline__ void cpcommit() {
    asm volatile("cp.async.commit_group;" ::: "memory");
}
__device__ __forceinline__ void cpwait0() {
    asm volatile("cp.async.wait_group 0;" ::: "memory");
}
__device__ __forceinline__ void cpwait1() {
    asm volatile("cp.async.wait_group 1;" ::: "memory");
}
__device__ __forceinline__ void cpwait2() {
    asm volatile("cp.async.wait_group 2;" ::: "memory");
}

// ---------------- misc small kernels -----------------------------------------
__global__ void bias_concat_kernel(const float* bq, const float* bk,
                                   const float* bv, float* out)
{
    const int i = blockIdx.x * 256 + threadIdx.x;
    float v;
    if (i < 1024)      v = bq[i];
    else if (i < 2048) v = bk[i - 1024];
    else               v = bv[i - 2048];
    out[i] = v;
}

// transpose v2: 32x32 tiles (1024+ blocks), float4 loads, uint2 (4-half) stores
// out[c][r] = fp16(in[r][c])
__global__ __launch_bounds__(256) void transpose_hv_kernel(
    const float* __restrict__ in, __half* __restrict__ o, int R, int Cc)
{
    __shared__ float ts[32][33];
    const int t  = threadIdx.x;
    const int c0 = blockIdx.x * 32, r0 = blockIdx.y * 32;

    {
        const int row = t >> 3, c4 = t & 7;
        float4 f = *reinterpret_cast<const float4*>(
            in + (size_t)(r0 + row) * Cc + c0 + c4 * 4);
        ts[row][c4*4+0] = f.x; ts[row][c4*4+1] = f.y;
        ts[row][c4*4+2] = f.z; ts[row][c4*4+3] = f.w;
    }
    __syncthreads();
    {
        const int cc = t >> 3, g = t & 7;
        uint2 w = { pckf(ts[4*g+0][cc], ts[4*g+1][cc]),
                    pckf(ts[4*g+2][cc], ts[4*g+3][cc]) };
        *reinterpret_cast<uint2*>(o + (size_t)(c0 + cc) * R + r0 + 4 * g) = w;
    }
}

// QKV variant: gridDim.z selects wq/wk/wv -> concat dst (homogeneous dispatch)
__global__ __launch_bounds__(256) void transpose_hv_qkv_kernel(
    const float* __restrict__ wq, const float* __restrict__ wk,
    const float* __restrict__ wv, __half* __restrict__ o)
{
    __shared__ float ts[32][33];
    const int t   = threadIdx.x;
    const int sec = blockIdx.z;
    const int c0  = blockIdx.x * 32, r0 = blockIdx.y * 32;
    const float* in = (sec == 0) ? wq : (sec == 1) ? wk : wv;
    __half* dst = o + (size_t)sec * CDIM * CDIM;

    {
        const int row = t >> 3, c4 = t & 7;
        float4 f = *reinterpret_cast<const float4*>(
            in + (size_t)(r0 + row) * CDIM + c0 + c4 * 4);
        ts[row][c4*4+0] = f.x; ts[row][c4*4+1] = f.y;
        ts[row][c4*4+2] = f.z; ts[row][c4*4+3] = f.w;
    }
    __syncthreads();
    {
        const int cc = t >> 3, g = t & 7;
        uint2 w = { pckf(ts[4*g+0][cc], ts[4*g+1][cc]),
                    pckf(ts[4*g+2][cc], ts[4*g+3][cc]) };
        *reinterpret_cast<uint2*>(dst + (size_t)(c0 + cc) * CDIM + r0 + 4 * g) = w;
    }
}

__global__ __launch_bounds__(256) void rmsnorm_h_kernel(
    const float* __restrict__ x, const float* __restrict__ scale,
    __half* __restrict__ o)
{
    __shared__ float red[8];
    const int row = blockIdx.x;
    const int t   = threadIdx.x;
    const float* xr = x + (size_t)row * CDIM;

    float4 v = *reinterpret_cast<const float4*>(xr + t * 4);
    float ss = v.x * v.x + v.y * v.y + v.z * v.z + v.w * v.w;
    #pragma unroll
    for (int of = 16; of > 0; of >>= 1) ss += __shfl_xor_sync(0xffffffffu, ss, of);
    if ((t & 31) == 0) red[t >> 5] = ss;
    __syncthreads();
    if (t < 8) {
        float s2 = red[t];
        #pragma unroll
        for (int of = 4; of > 0; of >>= 1) s2 += __shfl_xor_sync(0xffu, s2, of);
        if (t == 0) red[0] = s2;
    }
    __syncthreads();
    const float norm = sqrtf(red[0]);
    const float inv  = 1.0f / (norm * 0.03125f + 1e-8f);

    float4 sc = *reinterpret_cast<const float4*>(scale + t * 4);
    uint2 w;
    w.x = pckf(v.x * sc.x * inv, v.y * sc.y * inv);
    w.y = pckf(v.z * sc.z * inv, v.w * sc.w * inv);
    *reinterpret_cast<uint2*>(o + (size_t)row * CDIM + t * 4) = w;
}

// ---------------- GEMM v4 + EPI 4 fused QKV rotary (R12 verbatim) -----------
#define PITCH 40
#define TILEB (128 * PITCH * 2)     // 10240 B
#define STAGEB (2 * TILEB)          // 20480 B (A + B)
#define GSMEM (3 * STAGEB)          // 61440 B

template <int EPI>
__global__ __launch_bounds__(256, 2) void gemm4_kernel(
    const __half* __restrict__ A, const __half* __restrict__ Bw,
    const float* __restrict__ bias, const float* __restrict__ res,
    float* __restrict__ Co, __half* __restrict__ Ch,
    __half* __restrict__ Qd, __half* __restrict__ Kd, __half* __restrict__ Vd,
    int M, int Nn, int K)
{
    extern __shared__ char sm[];
    const uint32_t sbase = smem_u32(sm);

    const int t    = threadIdx.x;
    const int lane = t & 31;
    const int warp = t >> 5;
    const int wm   = (warp & 3) * 32;
    const int wn   = (warp >> 2) * 64;
    const int bm   = blockIdx.y * 128;
    const int bn   = blockIdx.x * 128;

    const uint32_t aoffA =
        ((wm + (lane & 15)) * PITCH + ((lane >> 4) * 8)) * 2;
    const uint32_t aoffB =
        ((wn + (lane & 7) + ((lane >> 4) << 3)) * PITCH + (((lane >> 3) & 1) * 8)) * 2;

    float acc[2][8][4];
    #pragma unroll
    for (int mi = 0; mi < 2; mi++)
        #pragma unroll
        for (int j = 0; j < 8; j++)
            #pragma unroll
            for (int q = 0; q < 4; q++) acc[mi][j][q] = 0.0f;

    const int KT = K / 32;

    #define G_ISSUE(kt, stg)                                                  \
        { const uint32_t sb = sbase + (uint32_t)(stg) * STAGEB;               \
          const int row = t >> 1, c = t & 1;                                  \
          const uint32_t d = sb + row * (PITCH * 2) + c * 32;                 \
          const size_t ga = (size_t)(bm + row) * K + (kt) * 32 + c * 16;      \
          const size_t gb = (size_t)(bn + row) * K + (kt) * 32 + c * 16;      \
          cp16(d,              A  + ga);                                      \
          cp16(d + 16,         A  + ga + 8);                                  \
          cp16(d + TILEB,      Bw + gb);                                      \
          cp16(d + TILEB + 16, Bw + gb + 8);                                  \
        }

    G_ISSUE(0, 0); cpcommit();
    G_ISSUE(1, 1); cpcommit();

    int stg = 0;
    for (int kt = 0; kt < KT; kt++) {
        if (kt + 1 < KT) cpwait1(); else cpwait0();
        __syncthreads();

        const uint32_t sA = sbase + (uint32_t)stg * STAGEB;
        const uint32_t sB = sA + TILEB;

        #pragma unroll
        for (int ks = 0; ks < 2; ks++) {
            uint32_t af[2][4];
            ldmat4(af[0], sA + aoffA + ks * 32);
            ldmat4(af[1], sA + aoffA + 16 * PITCH * 2 + ks * 32);
            #pragma unroll
            for (int p = 0; p < 4; p++) {
                uint32_t bf4[4];
                ldmat4(bf4, sB + aoffB + p * 16 * PITCH * 2 + ks * 32);
                #pragma unroll
                for (int mi = 0; mi < 2; mi++) {
                    mma16816(acc[mi][2*p],   af[mi], bf4[0], bf4[1]);
                    mma16816(acc[mi][2*p+1], af[mi], bf4[2], bf4[3]);
                }
            }
        }

        if (kt + 2 < KT) {
            const int ns = (stg + 2 >= 3) ? stg - 1 : stg + 2;
            G_ISSUE(kt + 2, ns); cpcommit();
        }
        stg = (stg + 1 == 3) ? 0 : stg + 1;
    }
    #undef G_ISSUE

    const int r0 = bm + wm + (lane >> 2);
    const int cb = bn + wn + (lane & 3) * 2;

    if (EPI == 4) {
        const float cscale = 0.125f * 1.4426950408889634f;
        const int secc    = (bn + wn) >> 10;                 // 0=q 1=k 2=v
        __half* dst = (secc == 0) ? Qd : (secc == 1) ? Kd : Vd;
        const int colbase = ((bn + wn) & 1023) + (lane & 3) * 2;
        const int srcl    = (lane & ~3) | ((lane + 3) & 3);
        const int q4      = lane & 3;
        #pragma unroll
        for (int mi = 0; mi < 2; mi++) {
            float a0[8], a1[8], c0[8], c1[8];
            #pragma unroll
            for (int j = 0; j < 8; j++) {
                const int col = cb + j * 8;
                const float b0v = bias[col], b1v = bias[col + 1];
                a0[j] = acc[mi][j][0] + b0v;
                a1[j] = acc[mi][j][1] + b1v;
                c0[j] = acc[mi][j][2] + b0v;
                c1[j] = acc[mi][j][3] + b1v;
            }
            const int ra = r0 + mi * 16, rb = ra + 8;
            if (secc == 2) {
                #pragma unroll
                for (int j = 0; j < 8; j++) {
                    const int cc = colbase + j * 8;
                    *reinterpret_cast<uint32_t*>(dst + (size_t)ra * CDIM + cc) =
                        pckf(a0[j], a1[j]);
                    *reinterpret_cast<uint32_t*>(dst + (size_t)rb * CDIM + cc) =
                        pckf(c0[j], c1[j]);
                }
            } else {
                float pa[8], pc[8];
                #pragma unroll
                for (int j = 0; j < 8; j++) {
                    pa[j] = __shfl_sync(0xffffffffu, a1[j], srcl);
                    pc[j] = __shfl_sync(0xffffffffu, c1[j], srcl);
                }
                #pragma unroll
                for (int j = 0; j < 8; j++) {
                    const float prevA = q4 ? pa[j] : pa[(j + 7) & 7];
                    const float prevC = q4 ? pc[j] : pc[(j + 7) & 7];
                    float oA0 = a0[j] - prevA, oA1 = a1[j] - a0[j];
                    float oC0 = c0[j] - prevC, oC1 = c1[j] - c0[j];
                    if (secc == 0) {
                        oA0 *= cscale; oA1 *= cscale;
                        oC0 *= cscale; oC1 *= cscale;
                    }
                    const int cc = colbase + j * 8;
                    *reinterpret_cast<uint32_t*>(dst + (size_t)ra * CDIM + cc) =
                        pckf(oA0, oA1);
                    *reinterpret_cast<uint32_t*>(dst + (size_t)rb * CDIM + cc) =
                        pckf(oC0, oC1);
                }
            }
        }
        return;
    }

    #pragma unroll
    for (int mi = 0; mi < 2; mi++) {
        #pragma unroll
        for (int j = 0; j < 8; j++) {
            const int col = cb + j * 8;
            const float b0v = bias[col], b1v = bias[col + 1];
            const int ra = r0 + mi * 16, rb = ra + 8;
            float2 v0 = { acc[mi][j][0] + b0v, acc[mi][j][1] + b1v };
            float2 v1 = { acc[mi][j][2] + b0v, acc[mi][j][3] + b1v };
            if (EPI == 1) {
                const float2 ra2 = *reinterpret_cast<const float2*>(
                    res + (size_t)ra * Nn + col);
                const float2 rb2 = *reinterpret_cast<const float2*>(
                    res + (size_t)rb * Nn + col);
                v0.x += ra2.x; v0.y += ra2.y; v1.x += rb2.x; v1.y += rb2.y;
            }
            if (EPI == 2) {
                *reinterpret_cast<uint32_t*>(Ch + (size_t)ra * Nn + col) =
                    pckf(gelu_exact(v0.x), gelu_exact(v0.y));
                *reinterpret_cast<uint32_t*>(Ch + (size_t)rb * Nn + col) =
                    pckf(gelu_exact(v1.x), gelu_exact(v1.y));
            } else if (EPI == 3) {
                *reinterpret_cast<uint32_t*>(Ch + (size_t)ra * Nn + col) =
                    pckf(v0.x, v0.y);
                *reinterpret_cast<uint32_t*>(Ch + (size_t)rb * Nn + col) =
                    pckf(v1.x, v1.y);
            } else {
                *reinterpret_cast<float2*>(Co + (size_t)ra * Nn + col) = v0;
                *reinterpret_cast<float2*>(Co + (size_t)rb * Nn + col) = v1;
            }
        }
    }
}

// ---------------- flash attention v4 (R10 verbatim) --------------------------
#define APITCH 72
#define ATILE  (64 * APITCH * 2)
#define QTILE  (128 * APITCH * 2)
#define ASMEM  (QTILE + 3 * 2 * ATILE)

__global__ __launch_bounds__(256) void flash_attn4_kernel(
    const __half* __restrict__ q, const __half* __restrict__ k,
    const __half* __restrict__ v, __half* __restrict__ o)
{
    extern __shared__ char shm[];
    const uint32_t sbase = smem_u32(shm);
    const uint32_t kvb0  = sbase + QTILE;

    const int t    = threadIdx.x;
    const int lane = t & 31;
    const int warp = t >> 5;
    const int b    = blockIdx.y >> 4;
    const int h    = blockIdx.y & 15;
    const int q0   = blockIdx.x * 128;
    const int wm   = warp * 16;

    #pragma unroll
    for (int i = 0; i < 4; i++) {
        const int idx = i * 256 + t;
        const int row = idx >> 3, c = idx & 7;
        cp16(sbase + row * (APITCH * 2) + c * 16,
             q + (size_t)(b * NSEQ + q0 + row) * CDIM + h * HDIM + c * 8);
    }
    cpcommit();

    #define KV_ISSUE(kt, stg)                                                 \
        { const uint32_t sb = kvb0 + (uint32_t)(stg) * 2 * ATILE;             \
          _Pragma("unroll")                                                   \
          for (int i = 0; i < 2; i++) {                                       \
              const int idx = i * 256 + t;                                    \
              const int row = idx >> 3, c = idx & 7;                          \
              const size_t g = (size_t)(b * NSEQ + (kt) * 64 + row) * CDIM    \
                               + h * HDIM + c * 8;                            \
              const uint32_t d = sb + row * (APITCH * 2) + c * 16;            \
              cp16(d,         k + g);                                        \
              cp16(d + ATILE, v + g);                                        \
          } }

    KV_ISSUE(0, 0); cpcommit();
    KV_ISSUE(1, 1); cpcommit();
    cpwait2();
    __syncthreads();

    uint32_t qf[4][4];
    #pragma unroll
    for (int ks = 0; ks < 4; ks++)
        ldmat4(qf[ks], sbase + ((wm + (lane & 15)) * APITCH + ks * 16
                                + (lane >> 4) * 8) * 2);

    float m0 = -1e30f, m1 = -1e30f, l0 = 0.0f, l1 = 0.0f;
    float oa[8][4];
    #pragma unroll
    for (int j = 0; j < 8; j++)
        #pragma unroll
        for (int p = 0; p < 4; p++) oa[j][p] = 0.0f;

    const uint32_t one2 = 0x3C003C00u;
    const int NT = NSEQ / 64;
    int stg = 0;
    for (int kt = 0; kt < NT; kt++) {
        if (kt + 1 < NT) cpwait1(); else cpwait0();
        __syncthreads();

        const uint32_t kb = kvb0 + (uint32_t)stg * 2 * ATILE;
        const uint32_t vb = kb + ATILE;

        float sc[8][4];
        #pragma unroll
        for (int j = 0; j < 8; j++)
            #pragma unroll
            for (int p = 0; p < 4; p++) sc[j][p] = 0.0f;

        #pragma unroll
        for (int ks = 0; ks < 4; ks++) {
            #pragma unroll
            for (int p = 0; p < 4; p++) {
                uint32_t r4[4];
                ldmat4(r4, kb + ((p * 16 + (lane & 7) + ((lane >> 4) << 3)) * APITCH
                                 + ks * 16 + ((lane >> 3) & 1) * 8) * 2);
                mma16816(sc[2*p],   qf[ks], r4[0], r4[1]);
                mma16816(sc[2*p+1], qf[ks], r4[2], r4[3]);
            }
        }

        float mx0 = sc[0][0], mx1 = sc[0][2];
        #pragma unroll
        for (int j = 0; j < 8; j++) {
            mx0 = fmaxf(mx0, fmaxf(sc[j][0], sc[j][1]));
            mx1 = fmaxf(mx1, fmaxf(sc[j][2], sc[j][3]));
        }
        mx0 = fmaxf(mx0, __shfl_xor_sync(0xffffffffu, mx0, 1));
        mx0 = fmaxf(mx0, __shfl_xor_sync(0xffffffffu, mx0, 2));
        mx1 = fmaxf(mx1, __shfl_xor_sync(0xffffffffu, mx1, 1));
        mx1 = fmaxf(mx1, __shfl_xor_sync(0xffffffffu, mx1, 2));

        const float mn0 = fmaxf(m0, mx0), mn1 = fmaxf(m1, mx1);
        const float cr0 = ex2f(m0 - mn0), cr1 = ex2f(m1 - mn1);
        m0 = mn0; m1 = mn1;

        uint32_t pf[4][4];
        #pragma unroll
        for (int j = 0; j < 8; j++) {
            const float d0 = sc[j][0] - mn0;
            const float d1 = sc[j][1] - mn0;
            const float d2 = sc[j][2] - mn1;
            const float d3 = sc[j][3] - mn1;
            uint32_t c01, c23;
            asm("cvt.rn.f16x2.f32 %0, %1, %2;" : "=r"(c01) : "f"(d1), "f"(d0));
            asm("cvt.rn.f16x2.f32 %0, %1, %2;" : "=r"(c23) : "f"(d3), "f"(d2));
            uint32_t p01, p23;
            asm("ex2.approx.f16x2 %0, %1;" : "=r"(p01) : "r"(c01));
            asm("ex2.approx.f16x2 %0, %1;" : "=r"(p23) : "r"(c23));
            pf[j >> 1][(j & 1) * 2 + 0] = p01;
            pf[j >> 1][(j & 1) * 2 + 1] = p23;
        }

        float ls[4] = {0.0f, 0.0f, 0.0f, 0.0f};
        #pragma unroll
        for (int ks = 0; ks < 4; ks++) mma16816(ls, pf[ks], one2, one2);
        l0 = l0 * cr0 + ls[0];
        l1 = l1 * cr1 + ls[2];

        #pragma unroll
        for (int j = 0; j < 8; j++) {
            oa[j][0] *= cr0; oa[j][1] *= cr0;
            oa[j][2] *= cr1; oa[j][3] *= cr1;
        }

        #pragma unroll
        for (int ks = 0; ks < 4; ks++) {
            #pragma unroll
            for (int p = 0; p < 4; p++) {
                uint32_t r4[4];
                ldmat4t(r4, vb + ((ks * 16 + (lane & 15)) * APITCH
                                  + p * 16 + ((lane >> 4) << 3)) * 2);
                mma16816(oa[2*p],   pf[ks], r4[0], r4[1]);
                mma16816(oa[2*p+1], pf[ks], r4[2], r4[3]);
            }
        }

        if (kt + 2 < NT) {
            const int ns = (stg + 2 >= 3) ? stg - 1 : stg + 2;
            KV_ISSUE(kt + 2, ns); cpcommit();
        }
        stg = (stg + 1 == 3) ? 0 : stg + 1;
    }
    #undef KV_ISSUE

    const float iv0 = 1.0f / l0, iv1 = 1.0f / l1;
    const int ra = q0 + wm + (lane >> 2);
    const int rb = ra + 8;
    #pragma unroll
    for (int j = 0; j < 8; j++) {
        const int col = h * HDIM + j * 8 + (lane & 3) * 2;
        *reinterpret_cast<uint32_t*>(o + (size_t)(b * NSEQ + ra) * CDIM + col) =
            pckf(oa[j][0] * iv0, oa[j][1] * iv0);
        *reinterpret_cast<uint32_t*>(o + (size_t)(b * NSEQ + rb) * CDIM + col) =
            pckf(oa[j][2] * iv1, oa[j][3] * iv1);
    }
}

// ---------------- host orchestration ----------------------------------------
extern "C" void kernel_launch(void* const* d_in, const int* in_sizes, int n_in,
                              void* d_out, int out_size)
{
    const float* x      = (const float*)d_in[0];
    const float* wq     = (const float*)d_in[1];
    const float* bq     = (const float*)d_in[2];
    const float* wk     = (const float*)d_in[3];
    const float* bk     = (const float*)d_in[4];
    const float* wv     = (const float*)d_in[5];
    const float* bv     = (const float*)d_in[6];
    const float* wo     = (const float*)d_in[7];
    const float* bo     = (const float*)d_in[8];
    const float* scale1 = (const float*)d_in[9];
    const float* scale2 = (const float*)d_in[10];
    const float* w1     = (const float*)d_in[11];
    const float* b1     = (const float*)d_in[12];
    const float* w2     = (const float*)d_in[13];
    const float* b2     = (const float*)d_in[14];
    float* out = (float*)d_out;

    __half *p_xn, *p_qb, *p_kb, *p_vb, *p_ctx, *p_xn2, *p_h;
    __half *p_wqkv, *p_wo, *p_w1, *p_w2;
    float *p_x2, *p_bqkv;
    cudaGetSymbolAddress((void**)&p_xn,   g_xn);
    cudaGetSymbolAddress((void**)&p_qb,   g_qb);
    cudaGetSymbolAddress((void**)&p_kb,   g_kb);
    cudaGetSymbolAddress((void**)&p_vb,   g_vb);
    cudaGetSymbolAddress((void**)&p_ctx,  g_ctx);
    cudaGetSymbolAddress((void**)&p_x2,   g_x2);
    cudaGetSymbolAddress((void**)&p_xn2,  g_xn2);
    cudaGetSymbolAddress((void**)&p_h,    g_h);
    cudaGetSymbolAddress((void**)&p_wqkv, g_wqkv);
    cudaGetSymbolAddress((void**)&p_wo,   g_wo);
    cudaGetSymbolAddress((void**)&p_w1,   g_w1);
    cudaGetSymbolAddress((void**)&p_w2,   g_w2);
    cudaGetSymbolAddress((void**)&p_bqkv, g_bqkv);

    cudaFuncSetAttribute(gemm4_kernel<1>,
                         cudaFuncAttributeMaxDynamicSharedMemorySize, GSMEM);
    cudaFuncSetAttribute(gemm4_kernel<2>,
                         cudaFuncAttributeMaxDynamicSharedMemorySize, GSMEM);
    cudaFuncSetAttribute(gemm4_kernel<4>,
                         cudaFuncAttributeMaxDynamicSharedMemorySize, GSMEM);
    cudaFuncSetAttribute(flash_attn4_kernel,
                         cudaFuncAttributeMaxDynamicSharedMemorySize, ASMEM);

    bias_concat_kernel<<<QKVN / 256, 256>>>(bq, bk, bv, p_bqkv);
    // all three QKV weight transposes in one launch (grid.z = 3)
    transpose_hv_qkv_kernel<<<dim3(CDIM/32, CDIM/32, 3), 256>>>(
        wq, wk, wv, p_wqkv);
    rmsnorm_h_kernel<<<MTOT, 256>>>(x, scale1, p_xn);
    // fused QKV GEMM with rotary/scale/scatter epilogue
    gemm4_kernel<4><<<dim3(QKVN/128, MTOT/128), 256, GSMEM>>>(
        p_xn, p_wqkv, p_bqkv, nullptr, nullptr, nullptr,
        p_qb, p_kb, p_vb, MTOT, QKVN, CDIM);
    flash_attn4_kernel<<<dim3(NSEQ/128, 2*NHEAD), 256, ASMEM>>>(
        p_qb, p_kb, p_vb, p_ctx);
    transpose_hv_kernel<<<dim3(CDIM/32, CDIM/32), 256>>>(wo, p_wo, CDIM, CDIM);
    gemm4_kernel<1><<<dim3(CDIM/128, MTOT/128), 256, GSMEM>>>(
        p_ctx, p_wo, bo, x, p_x2, nullptr,
        nullptr, nullptr, nullptr, MTOT, CDIM, CDIM);
    rmsnorm_h_kernel<<<MTOT, 256>>>(p_x2, scale2, p_xn2);
    transpose_hv_kernel<<<dim3(FFDIM/32, CDIM/32), 256>>>(w1, p_w1, CDIM, FFDIM);
    gemm4_kernel<2><<<dim3(FFDIM/128, MTOT/128), 256, GSMEM>>>(
        p_xn2, p_w1, b1, nullptr, nullptr, p_h,
        nullptr, nullptr, nullptr, MTOT, FFDIM, CDIM);
    transpose_hv_kernel<<<dim3(CDIM/32, FFDIM/32), 256>>>(w2, p_w2, FFDIM, CDIM);
    gemm4_kernel<1><<<dim3(CDIM/128, MTOT/128), 256, GSMEM>>>(
        p_h, p_w2, b2, p_x2, out, nullptr,
        nullptr, nullptr, nullptr, MTOT, CDIM, FFDIM);
}